// round 4
// baseline (speedup 1.0000x reference)
#include <cuda_runtime.h>

// SoftDepthShader: per-pixel softmax depth blend over K=50 raster slots.
// out[p] = (sum_k w_k * zbuf_k + delta) / (sum_k w_k + delta)
//   mask_k  = pix_to_face_k >= 0       (pix_to_face is int32 on device: JAX x64 disabled)
//   prob_k  = sigmoid(-dists_k/SIGMA) * mask_k
//   zinv_k  = (ZFAR - zbuf_k)/(ZFAR - ZNEAR) * mask_k
//   zmax    = max(max_k zinv_k, EPS)
//   w_k     = prob_k * exp((zinv_k - zmax)/GAMMA)
//   delta   = max(exp((EPS - zmax)/GAMMA), EPS)
//
// HBM-bound streaming kernel: 16 lanes per pixel, 4 K-slots per lane,
// single pass over memory with register-resident slot state, shfl reductions.

#define KSLOTS   50
#define LANES_PP 16      // lanes per pixel
#define KPL      4       // ceil(50/16)

__global__ __launch_bounds__(256)
void soft_depth_kernel(const float* __restrict__ zbuf,
                       const float* __restrict__ dists,
                       const int* __restrict__ p2f,
                       float* __restrict__ out,
                       int npix)
{
    const float INV_SIGMA   = 1e4f;            // 1/SIGMA
    const float INV_GAMMA   = 1e4f;            // 1/GAMMA
    const float ZFAR        = 100.0f;
    const float INV_ZRANGE  = 1.0f / (100.0f - 1.0f);
    const float EPS         = 1e-10f;

    int tid = blockIdx.x * blockDim.x + threadIdx.x;
    int pix = tid >> 4;          // /16
    int sub = tid & 15;
    if (pix >= npix) return;

    size_t base = (size_t)pix * KSLOTS;
    const float* zb = zbuf  + base;
    const float* ds = dists + base;
    const int*   pf = p2f   + base;

    float zv[KPL], pr[KPL], zi[KPL];
    float zmax = 0.0f;

    #pragma unroll
    for (int i = 0; i < KPL; i++) {
        int k = sub + LANES_PP * i;
        bool in = (k < KSLOTS);
        float z = 0.0f, d = 0.0f;
        int   f = -1;
        if (in) {
            z = __ldcs(zb + k);
            d = __ldcs(ds + k);
            f = __ldcs(pf + k);
        }
        float m    = (f >= 0) ? 1.0f : 0.0f;
        float prob = m / (1.0f + __expf(d * INV_SIGMA));   // sigmoid(-d/sigma)*m
        float zinv = (ZFAR - z) * INV_ZRANGE * m;
        zv[i] = z; pr[i] = prob; zi[i] = zinv;
        zmax = fmaxf(zmax, zinv);
    }

    // 16-lane group max (lanes of one pixel are contiguous within the warp)
    #pragma unroll
    for (int o = 8; o; o >>= 1)
        zmax = fmaxf(zmax, __shfl_xor_sync(0xffffffffu, zmax, o));
    zmax = fmaxf(zmax, EPS);

    float num = 0.0f, den = 0.0f;
    #pragma unroll
    for (int i = 0; i < KPL; i++) {
        float w = pr[i] * __expf((zi[i] - zmax) * INV_GAMMA);
        den += w;
        num += w * zv[i];
    }
    #pragma unroll
    for (int o = 8; o; o >>= 1) {
        den += __shfl_xor_sync(0xffffffffu, den, o);
        num += __shfl_xor_sync(0xffffffffu, num, o);
    }

    if (sub == 0) {
        float delta = fmaxf(__expf((EPS - zmax) * INV_GAMMA), EPS);
        out[pix] = (num + delta) / (den + delta);   // BG_BLUE = 1
    }
}

extern "C" void kernel_launch(void* const* d_in, const int* in_sizes, int n_in,
                              void* d_out, int out_size)
{
    const float* zbuf  = (const float*)d_in[0];
    const float* dists = (const float*)d_in[1];
    const int*   p2f   = (const int*)d_in[2];
    float*       out   = (float*)d_out;

    int npix = in_sizes[0] / KSLOTS;               // 8*256*256 = 524288
    int threads = 256;
    long long total = (long long)npix * LANES_PP;  // 16 threads per pixel
    int blocks = (int)((total + threads - 1) / threads);

    soft_depth_kernel<<<blocks, threads>>>(zbuf, dists, p2f, out, npix);
}

// round 5
// speedup vs baseline: 1.6344x; 1.6344x over previous
#include <cuda_runtime.h>

// SoftDepthShader: per-pixel softmax depth blend over K=50 raster slots.
// out[p] = (sum_k w_k * z_k + delta) / (sum_k w_k + delta)
//   mask_k = pix_to_face_k >= 0  (int32 on device)
//   prob_k = sigmoid(-dists_k/SIGMA) * mask_k
//   zinv_k = (ZFAR - z_k)/(ZFAR-ZNEAR) * mask_k
//   zmax   = max(max_k zinv_k, EPS)
//   w_k    = prob_k * exp((zinv_k - zmax)/GAMMA)
//   delta  = max(exp((EPS - zmax)/GAMMA), EPS)
//
// Issue-optimized streaming kernel: float2/int2 vectorized loads,
// 8 lanes per pixel x 4 float2-slots per lane, fast reciprocal sigmoid,
// z reconstructed from zinv in pass 2 (masked slots have w=0).

#define KSLOTS   50
#define SLOT2    25      // float2 slots per pixel
#define LANES_PP 8
#define SPL      4       // slots per lane (ceil(25/8))

__global__ __launch_bounds__(256)
void soft_depth_kernel(const float2* __restrict__ zbuf,
                       const float2* __restrict__ dists,
                       const int2*   __restrict__ p2f,
                       float* __restrict__ out,
                       int npix)
{
    const float INV_SIGMA  = 1e4f;
    const float INV_GAMMA  = 1e4f;
    const float ZFAR       = 100.0f;
    const float ZRANGE     = 99.0f;
    const float INV_ZRANGE = 1.0f / 99.0f;
    const float EPS        = 1e-10f;

    int tid = blockIdx.x * blockDim.x + threadIdx.x;
    int pix = tid >> 3;         // /8
    int sub = tid & 7;
    if (pix >= npix) return;

    size_t base = (size_t)pix * SLOT2;
    const float2* zb = zbuf  + base;
    const float2* ds = dists + base;
    const int2*   pf = p2f   + base;

    float pr[2 * SPL], zi[2 * SPL];
    float zmax = 0.0f;

    #pragma unroll
    for (int i = 0; i < SPL; i++) {
        int s = sub + LANES_PP * i;
        bool in = (s < SLOT2);
        float2 z = make_float2(0.0f, 0.0f);
        float2 d = make_float2(0.0f, 0.0f);
        int2   f = make_int2(-1, -1);
        if (in) {
            z = __ldcs(zb + s);
            d = __ldcs(ds + s);
            f = __ldcs(pf + s);
        }
        float m0 = (f.x >= 0) ? 1.0f : 0.0f;
        float m1 = (f.y >= 0) ? 1.0f : 0.0f;
        float e0 = __expf(d.x * INV_SIGMA);
        float e1 = __expf(d.y * INV_SIGMA);
        float p0 = m0 * __fdividef(1.0f, 1.0f + e0);  // sigmoid(-d/sigma)*m
        float p1 = m1 * __fdividef(1.0f, 1.0f + e1);
        float v0 = (ZFAR - z.x) * INV_ZRANGE * m0;
        float v1 = (ZFAR - z.y) * INV_ZRANGE * m1;
        pr[2*i]   = p0;  zi[2*i]   = v0;
        pr[2*i+1] = p1;  zi[2*i+1] = v1;
        zmax = fmaxf(zmax, fmaxf(v0, v1));
    }

    // 8-lane group max (lanes of one pixel contiguous within warp)
    #pragma unroll
    for (int o = 4; o; o >>= 1)
        zmax = fmaxf(zmax, __shfl_xor_sync(0xffffffffu, zmax, o));
    zmax = fmaxf(zmax, EPS);

    float num = 0.0f, den = 0.0f;
    #pragma unroll
    for (int j = 0; j < 2 * SPL; j++) {
        float w = pr[j] * __expf((zi[j] - zmax) * INV_GAMMA);
        float z = fmaf(-zi[j], ZRANGE, ZFAR);  // reconstruct z; w=0 if masked
        den += w;
        num = fmaf(w, z, num);
    }
    #pragma unroll
    for (int o = 4; o; o >>= 1) {
        den += __shfl_xor_sync(0xffffffffu, den, o);
        num += __shfl_xor_sync(0xffffffffu, num, o);
    }

    if (sub == 0) {
        float delta = fmaxf(__expf((EPS - zmax) * INV_GAMMA), EPS);
        out[pix] = __fdividef(num + delta, den + delta);   // BG_BLUE = 1
    }
}

extern "C" void kernel_launch(void* const* d_in, const int* in_sizes, int n_in,
                              void* d_out, int out_size)
{
    const float2* zbuf  = (const float2*)d_in[0];
    const float2* dists = (const float2*)d_in[1];
    const int2*   p2f   = (const int2*)d_in[2];
    float*        out   = (float*)d_out;

    int npix = in_sizes[0] / KSLOTS;               // 8*256*256 = 524288
    int threads = 256;
    long long total = (long long)npix * LANES_PP;  // 8 threads per pixel
    int blocks = (int)((total + threads - 1) / threads);

    soft_depth_kernel<<<blocks, threads>>>(zbuf, dists, p2f, out, npix);
}